// round 6
// baseline (speedup 1.0000x reference)
#include <cuda_runtime.h>
#include <math.h>

#define BN   8
#define TT   12
#define NN   200
#define CIN  2
#define HH   64
#define DD   32
#define HST  64
#define GW   66      // CIN + HH
#define GIN  198     // GW * 3
#define GRID 148
#define NTH  1024

// ---------------- scratch (device globals; no allocation allowed) -------------
__device__ float g_state_dy[BN*NN*DD];
__device__ float g_state   [BN*NN*HH];
__device__ float g_Pg[BN*NN*DD];
__device__ float g_Qg[BN*NN*DD];
__device__ float g_Pm[BN*NN*DD];
__device__ float g_Qm[BN*NN*DD];
__device__ float g_A [BN*NN*NN];
__device__ float g_X1[BN*NN*GW];
__device__ float g_ru[BN*NN*2*HH];
__device__ float g_X0r[BN*NN*GW];   // [xt, state]       (ru path)
__device__ float g_X0c[BN*NN*GW];   // [xt, rr*state]    (cand path)
__device__ unsigned g_bar_gen;      // zero-init; monotonically increases across replays (safe)
__device__ unsigned g_bar_cnt;

__device__ __forceinline__ float fsig(float v){
    return __fdividef(1.f, 1.f + __expf(-v));
}

// classic fence+atomic grid barrier; all GRID blocks are co-resident (grid==#SM floor)
__device__ __forceinline__ void grid_barrier(){
    __syncthreads();
    if (threadIdx.x == 0){
        volatile unsigned* vgen = &g_bar_gen;
        unsigned gen = *vgen;
        __threadfence();
        if (atomicAdd(&g_bar_cnt, 1u) == GRID - 1u){
            g_bar_cnt = 0u;
            __threadfence();
            *vgen = gen + 1u;
        } else {
            while (*vgen == gen) { }
            __threadfence();
        }
    }
    __syncthreads();
}

// ---- hop: X1 = A @ X0  (8-row tiles, 10-way split-K, partials in smem) ------
__device__ __forceinline__ void hop_phase(float* sb, int bid, int tid,
                                          const float* __restrict__ X0)
{
    for (int iter = 0; iter < 2; iter++){
        int tile = iter*GRID + bid;
        bool act = tile < 200;
        int b = 0, i0 = 0;
        if (act){ b = tile/25; i0 = (tile - b*25)*8; }
        __syncthreads();
        if (act){
            const float* Ab = g_A + (b*NN + i0)*NN;
            for (int e = tid; e < 8*NN; e += NTH) sb[e] = Ab[e];
        }
        __syncthreads();
        if (act && tid < 660){
            int jg = tid/66, c = tid - jg*66;
            int j0 = jg*20;
            const float* X0b = X0 + b*NN*GW + c;
            float acc[8] = {0.f,0.f,0.f,0.f,0.f,0.f,0.f,0.f};
            for (int j = j0; j < j0 + 20; j += 2){
                float v0 = __ldg(X0b + j*GW);
                float v1 = __ldg(X0b + (j+1)*GW);
                #pragma unroll
                for (int il = 0; il < 8; il++){
                    float2 a = *(const float2*)&sb[il*NN + j];
                    acc[il] = fmaf(a.x, v0, acc[il]);
                    acc[il] = fmaf(a.y, v1, acc[il]);
                }
            }
            #pragma unroll
            for (int il = 0; il < 8; il++) sb[1600 + (jg*8 + il)*66 + c] = acc[il];
        }
        __syncthreads();
        if (act && tid < 528){
            int il = tid/66, c = tid - il*66;
            float s = 0.f;
            #pragma unroll
            for (int g = 0; g < 10; g++) s += sb[1600 + (g*8 + il)*66 + c];
            g_X1[(b*NN + i0 + il)*GW + c] = s;
        }
    }
}

// ---- conv: X2 = A@X1 (split-K) + Z=[X0,X1,X2] @ W + activation + epilogue ---
template<int FOUT, int CAND>
__device__ __forceinline__ void conv_phase(float* sb, int bid, int tid,
                                           const float* __restrict__ W,
                                           const float* __restrict__ bias)
{
    const float* __restrict__ X0 = CAND ? g_X0c : g_X0r;
    for (int iter = 0; iter < 2; iter++){
        int tile = iter*GRID + bid;
        bool act = tile < 200;
        int b = 0, i0 = 0;
        if (act){ b = tile/25; i0 = (tile - b*25)*8; }
        __syncthreads();
        if (act){
            const float* Ab = g_A + (b*NN + i0)*NN;
            for (int e = tid; e < 8*NN; e += NTH) sb[e] = Ab[e];
        }
        __syncthreads();
        if (act && tid < 660){
            int jg = tid/66, c = tid - jg*66;
            int j0 = jg*20;
            const float* X1b = g_X1 + b*NN*GW + c;
            float acc[8] = {0.f,0.f,0.f,0.f,0.f,0.f,0.f,0.f};
            for (int j = j0; j < j0 + 20; j += 2){
                float v0 = __ldg(X1b + j*GW);
                float v1 = __ldg(X1b + (j+1)*GW);
                #pragma unroll
                for (int il = 0; il < 8; il++){
                    float2 a = *(const float2*)&sb[il*NN + j];
                    acc[il] = fmaf(a.x, v0, acc[il]);
                    acc[il] = fmaf(a.y, v1, acc[il]);
                }
            }
            #pragma unroll
            for (int il = 0; il < 8; il++) sb[1600 + (jg*8 + il)*66 + c] = acc[il];
        }
        __syncthreads();
        if (act){
            for (int e = tid; e < 528; e += NTH){
                int il = e/66, c = e - il*66;
                float s = 0.f;
                #pragma unroll
                for (int g = 0; g < 10; g++) s += sb[1600 + (g*8 + il)*66 + c];
                int row = (b*NN + i0 + il)*GW + c;
                sb[6880 + il*GIN + 2*GW + c] = s;           // X2
                sb[6880 + il*GIN +   GW + c] = g_X1[row];   // X1
                sb[6880 + il*GIN +        c] = X0[row];     // X0
            }
        }
        __syncthreads();
        if (act && tid < FOUT){   // FOUT/2 f-pairs * 2 il-groups
            int f2  = tid % (FOUT/2);
            int ilg = tid / (FOUT/2);   // 0..1
            int il0 = ilg*4;
            const float2* Wv = (const float2*)W;
            float2 bb = ((const float2*)bias)[f2];
            float acc[4][2];
            #pragma unroll
            for (int q = 0; q < 4; q++){ acc[q][0] = bb.x; acc[q][1] = bb.y; }
            #pragma unroll 2
            for (int k = 0; k < GIN; k++){
                float2 w = Wv[k*(FOUT/2) + f2];
                #pragma unroll
                for (int q = 0; q < 4; q++){
                    float zv = sb[6880 + (il0 + q)*GIN + k];
                    acc[q][0] = fmaf(zv, w.x, acc[q][0]);
                    acc[q][1] = fmaf(zv, w.y, acc[q][1]);
                }
            }
            #pragma unroll
            for (int q = 0; q < 4; q++){
                int i = i0 + il0 + q;
                #pragma unroll
                for (int e2 = 0; e2 < 2; e2++){
                    int f = 2*f2 + e2;
                    float a = acc[q][e2];
                    if (!CAND){
                        float rv = fsig(a);
                        g_ru[(b*NN + i)*(2*HH) + f] = rv;
                        if (f < HH)
                            g_X0c[(b*NN + i)*GW + CIN + f] = rv * g_state[(b*NN + i)*HH + f];
                    } else {
                        float cv = tanhf(a);
                        float u  = g_ru[(b*NN + i)*(2*HH) + HH + f];
                        float so = g_state[(b*NN + i)*HH + f];
                        float ns = u*so + (1.f - u)*cv;
                        g_state[(b*NN + i)*HH + f] = ns;
                        g_X0r[(b*NN + i)*GW + CIN + f] = ns;
                    }
                }
            }
        }
    }
}

// ============================ megakernel =====================================
__global__ void __launch_bounds__(NTH, 1) mega_kernel(
    const float* __restrict__ x,     const float* __restrict__ nf,
    const float* __restrict__ W_s2d, const float* __restrict__ b_s2d,
    const float* __restrict__ W_rz,  const float* __restrict__ b_rz,
    const float* __restrict__ W_h,   const float* __restrict__ b_h,
    const float* __restrict__ Wc2,   const float* __restrict__ bc2,
    const float* __restrict__ Wc1,   const float* __restrict__ bc1,
    const float* __restrict__ Wm2,   const float* __restrict__ bm2,
    const float* __restrict__ Wm1,   const float* __restrict__ bm1,
    const float* __restrict__ W_ru,  const float* __restrict__ b_ru,
    const float* __restrict__ W_cand,const float* __restrict__ b_cand,
    const float* __restrict__ Wp1,   const float* __restrict__ bp1,
    const float* __restrict__ Wp2,   const float* __restrict__ bp2,
    float* __restrict__ out_pred,    float* __restrict__ out_dy)
{
    __shared__ float sb[8704];   // 34.8 KB, reused across phases
    int bid = blockIdx.x, tid = threadIdx.x;
    int warp = tid >> 5, lane = tid & 31;
    int gid = bid*NTH + tid;

    // ---------------- init ----------------
    for (int e = gid; e < NN*DD; e += GRID*NTH){
        int n = e/DD, d = e - (e/DD)*DD;
        float acc = b_s2d[d];
        for (int k = 0; k < HST; k++) acc = fmaf(nf[n*HST + k], W_s2d[k*DD + d], acc);
        for (int b = 0; b < BN; b++) g_state_dy[(b*NN + n)*DD + d] = acc;
    }
    for (int e = gid; e < BN*NN*HH; e += GRID*NTH) g_state[e] = 0.f;
    for (int e = gid; e < BN*NN*GW; e += GRID*NTH) g_X0r[e] = 0.f;
    grid_barrier();

    for (int t = 0; t < TT; t++){
        // ---------------- GRU-dy + P/Q (one warp per node) ----------------
        {
            int node = bid*32 + warp;
            if (node < BN*NN){
                int b = node/NN, n = node - (node/NN)*NN;
                float* sd = sb + warp*96;
                float* rs = sd + 32;
                float* sv = sd + 64;
                const float* xr = x + ((b*TT + t)*NN + n)*CIN;
                if (lane < CIN){
                    float xv = xr[lane];
                    g_X0r[(b*NN + n)*GW + lane] = xv;
                    g_X0c[(b*NN + n)*GW + lane] = xv;
                }
                float inp1 = xr[0];
                int base = node*DD;
                sd[lane] = g_state_dy[base + lane];
                __syncwarp();
                float accr = b_rz[lane]      + inp1 * W_rz[lane];
                float accz = b_rz[lane + 32] + inp1 * W_rz[lane + 32];
                #pragma unroll
                for (int d = 0; d < 32; d++){
                    float v = sd[d];
                    accr = fmaf(v, W_rz[(1 + d)*64 + lane],      accr);
                    accz = fmaf(v, W_rz[(1 + d)*64 + lane + 32], accz);
                }
                float r = fsig(accr), z = fsig(accz);
                rs[lane] = r * sd[lane];
                __syncwarp();
                float acch = b_h[lane] + inp1 * W_h[lane];
                #pragma unroll
                for (int d = 0; d < 32; d++) acch = fmaf(rs[d], W_h[(1 + d)*32 + lane], acch);
                float h  = tanhf(acch);
                float nd = z * sd[lane] + (1.f - z) * h;
                g_state_dy[base + lane] = nd;
                float s = fmaxf(nd, 0.f);
                sv[lane] = s;
                __syncwarp();
                float pg = 0.f, qg = bc2[lane], pm = 0.f, qm = bm2[lane];
                #pragma unroll
                for (int d = 0; d < 32; d++){
                    float v = sv[d];
                    pg = fmaf(v, Wc2[d*32 + lane],        pg);
                    qg = fmaf(v, Wc2[(32 + d)*32 + lane], qg);
                    pm = fmaf(v, Wm2[d*32 + lane],        pm);
                    qm = fmaf(v, Wm2[(32 + d)*32 + lane], qm);
                }
                g_Pg[base + lane] = pg;  g_Qg[base + lane] = qg;
                g_Pm[base + lane] = pm;  g_Qm[base + lane] = qm;
            }
        }
        grid_barrier();

        // ---------------- pair: A = g * sigmoid(m) ----------------
        {
            if (tid < 32){ sb[8448 + tid] = Wc1[tid]; sb[8480 + tid] = Wm1[tid]; }
            int grp = tid >> 8, t2 = tid & 255;
            float* Pgs = sb + grp*2112;
            float* Pms = Pgs + 528;
            float* Qgs = Pgs + 1056;
            float* Qms = Pgs + 1584;
            for (int iter = 0; iter < 3; iter++){
                int tile = iter*592 + bid*4 + grp;   // 13*13*8 = 1352 tiles
                bool act = tile < 1352;
                int b = 0, i0 = 0, j0 = 0;
                if (act){
                    b = tile/169;
                    int rem = tile - b*169;
                    i0 = (rem/13)*16; j0 = (rem - (rem/13)*13)*16;
                }
                __syncthreads();
                if (act){
                    for (int e = t2; e < 512; e += 256){
                        int il = e >> 5, d = e & 31;
                        int i = i0 + il, j = j0 + il;
                        if (i < NN){ int idx = (b*NN + i)*DD + d; Pgs[il*33 + d] = g_Pg[idx]; Pms[il*33 + d] = g_Pm[idx]; }
                        if (j < NN){ int idx = (b*NN + j)*DD + d; Qgs[il*33 + d] = g_Qg[idx]; Qms[il*33 + d] = g_Qm[idx]; }
                    }
                }
                __syncthreads();
                if (act){
                    int tj = t2 & 15, ti = t2 >> 4;
                    int i = i0 + ti, j = j0 + tj;
                    if (i < NN && j < NN){
                        float ga = bc1[0], ma = bm1[0];
                        #pragma unroll
                        for (int d = 0; d < 32; d++){
                            ga = fmaf(fmaxf(Pgs[ti*33 + d] + Qgs[tj*33 + d], 0.f), sb[8448 + d], ga);
                            ma = fmaf(fmaxf(Pms[ti*33 + d] + Qms[tj*33 + d], 0.f), sb[8480 + d], ma);
                        }
                        float A = ga * fsig(ma);
                        int idx = (b*NN + i)*NN + j;
                        g_A[idx] = A;
                        out_dy[(size_t)t*BN*NN*NN + idx] = A;
                    }
                }
            }
        }
        grid_barrier();

        hop_phase(sb, bid, tid, g_X0r);
        grid_barrier();
        conv_phase<128, 0>(sb, bid, tid, W_ru, b_ru);
        grid_barrier();
        hop_phase(sb, bid, tid, g_X0c);
        grid_barrier();
        conv_phase<64, 1>(sb, bid, tid, W_cand, b_cand);
        grid_barrier();
    }

    // ---------------- prediction head (one warp per node) ----------------
    {
        int node = bid*32 + warp;
        if (node < BN*NN){
            float s0 = g_state[node*HH + lane];
            float s1 = g_state[node*HH + 32 + lane];
            float a0 = bp1[lane], a1 = bp1[lane + 32];
            #pragma unroll
            for (int k = 0; k < 32; k++){
                float sk = __shfl_sync(0xffffffffu, s0, k);
                a0 = fmaf(sk, Wp1[k*HH + lane],      a0);
                a1 = fmaf(sk, Wp1[k*HH + lane + 32], a1);
            }
            #pragma unroll
            for (int k = 0; k < 32; k++){
                float sk = __shfl_sync(0xffffffffu, s1, k);
                a0 = fmaf(sk, Wp1[(32 + k)*HH + lane],      a0);
                a1 = fmaf(sk, Wp1[(32 + k)*HH + lane + 32], a1);
            }
            float h0 = a0 > 0.f ? a0 : 0.01f*a0;
            float h1 = a1 > 0.f ? a1 : 0.01f*a1;
            float r = h0*Wp2[lane] + h1*Wp2[lane + 32];
            #pragma unroll
            for (int off = 16; off > 0; off >>= 1) r += __shfl_down_sync(0xffffffffu, r, off);
            if (lane == 0) out_pred[node] = r + bp2[0];
        }
    }
}

// ---------------- launch ------------------------------------------------------
extern "C" void kernel_launch(void* const* d_in, const int* in_sizes, int n_in,
                              void* d_out, int out_size)
{
    (void)in_sizes; (void)n_in; (void)out_size;
    const float* x        = (const float*)d_in[0];
    const float* nf       = (const float*)d_in[1];
    const float* W_s2d    = (const float*)d_in[2];
    const float* b_s2d    = (const float*)d_in[3];
    const float* W_rz     = (const float*)d_in[4];
    const float* b_rz     = (const float*)d_in[5];
    const float* W_h      = (const float*)d_in[6];
    const float* b_h      = (const float*)d_in[7];
    const float* Wc2      = (const float*)d_in[8];
    const float* bc2      = (const float*)d_in[9];
    const float* Wc1      = (const float*)d_in[10];
    const float* bc1      = (const float*)d_in[11];
    const float* Wm2      = (const float*)d_in[12];
    const float* bm2      = (const float*)d_in[13];
    const float* Wm1      = (const float*)d_in[14];
    const float* bm1      = (const float*)d_in[15];
    const float* W_ru     = (const float*)d_in[16];
    const float* b_ru     = (const float*)d_in[17];
    const float* W_cand   = (const float*)d_in[18];
    const float* b_cand   = (const float*)d_in[19];
    const float* Wp1      = (const float*)d_in[20];
    const float* bp1      = (const float*)d_in[21];
    const float* Wp2      = (const float*)d_in[22];
    const float* bp2      = (const float*)d_in[23];

    float* out      = (float*)d_out;
    float* out_pred = out;                 // (B,N,1) = 1600 floats
    float* out_dy   = out + BN*NN;         // (T,B,N,N)

    mega_kernel<<<GRID, NTH>>>(x, nf, W_s2d, b_s2d, W_rz, b_rz, W_h, b_h,
                               Wc2, bc2, Wc1, bc1, Wm2, bm2, Wm1, bm1,
                               W_ru, b_ru, W_cand, b_cand,
                               Wp1, bp1, Wp2, bp2, out_pred, out_dy);
}

// round 8
// speedup vs baseline: 1.4765x; 1.4765x over previous
#include <cuda_runtime.h>
#include <math.h>

#define BN   8
#define TT   12
#define NN   200
#define CIN  2
#define HH   64
#define DD   32
#define HST  64
#define GW   66      // CIN + HH
#define GIN  198     // GW * 3
#define GROUPS 8
#define GPB    18
#define GRID   (GROUPS*GPB)   // 144 blocks, 1 per SM
#define NTH    1024

#define SMEMF  24576          // floats: A 2400 | Cp 19800 | Z 2376
#define OFF_CP 2400
#define OFF_Z  22200
// pair-phase smem offsets (disjoint use, same buffer)
#define P_PG 0
#define P_PM 2176
#define P_QG 4352
#define P_QM 5440
#define P_WG 6528
#define P_WM 6560

// ---------------- scratch (device globals; no allocation allowed) -------------
__device__ float g_state_dy[BN*NN*DD];
__device__ float g_state   [BN*NN*HH];
__device__ float g_Pg[BN*NN*DD];
__device__ float g_Qg[BN*NN*DD];
__device__ float g_Pm[BN*NN*DD];
__device__ float g_Qm[BN*NN*DD];
__device__ float g_A [BN*NN*NN];
__device__ float g_X1[BN*NN*GW];
__device__ float g_ru[BN*NN*2*HH];
__device__ float g_X0r[BN*NN*GW];   // [xt, state]
__device__ float g_X0c[BN*NN*GW];   // [xt, rr*state]
__device__ unsigned g_cnt[GROUPS];
__device__ unsigned g_gen[GROUPS];

__device__ __forceinline__ float fsig(float v){
    return __fdividef(1.f, 1.f + __expf(-v));
}

// group-local barrier among the GPB co-resident blocks of one group
__device__ __forceinline__ void group_barrier(int grp){
    __syncthreads();
    if (threadIdx.x == 0){
        volatile unsigned* vg = &g_gen[grp];
        unsigned gen = *vg;
        __threadfence();
        if (atomicAdd(&g_cnt[grp], 1u) == GPB - 1u){
            g_cnt[grp] = 0u;
            __threadfence();
            *vg = gen + 1u;
        } else {
            while (*vg == gen) { }
        }
        __threadfence();
    }
    __syncthreads();
}

// ---- hop: X1 = A @ X0 ; 12 rows/block, 25-way split-K, c-pair float2 acc ----
__device__ __forceinline__ void hop_phase(float* sb, int b, int rk, int tid,
                                          const float* __restrict__ X0)
{
    int row0 = rk*12;
    int nrows = (row0 < NN) ? ((NN - row0 < 12) ? NN - row0 : 12) : 0;
    if (nrows > 0){
        for (int e = tid; e < 12*NN; e += NTH){
            int il = e/NN, jj = e - il*NN;
            int r = row0 + (il < nrows ? il : nrows-1);
            sb[e] = g_A[(b*NN + r)*NN + jj];
        }
    }
    __syncthreads();
    if (nrows > 0 && tid < 825){
        int jg = tid/33, c2 = tid - jg*33;
        const float* X0b = X0 + b*NN*GW + 2*c2;
        float2 acc[12];
        #pragma unroll
        for (int il = 0; il < 12; il++){ acc[il].x = 0.f; acc[il].y = 0.f; }
        int j0 = jg*8;
        #pragma unroll
        for (int jp = 0; jp < 4; jp++){
            int j = j0 + jp*2;
            float2 x0 = *(const float2*)&X0b[j*GW];
            float2 x1 = *(const float2*)&X0b[(j+1)*GW];
            #pragma unroll
            for (int il = 0; il < 12; il++){
                float2 a = *(const float2*)&sb[il*NN + j];
                acc[il].x = fmaf(a.x, x0.x, acc[il].x);
                acc[il].y = fmaf(a.x, x0.y, acc[il].y);
                acc[il].x = fmaf(a.y, x1.x, acc[il].x);
                acc[il].y = fmaf(a.y, x1.y, acc[il].y);
            }
        }
        #pragma unroll
        for (int il = 0; il < 12; il++)
            *(float2*)&sb[OFF_CP + (jg*12 + il)*GW + 2*c2] = acc[il];
    }
    __syncthreads();
    if (nrows > 0){
        for (int e = tid; e < nrows*GW; e += NTH){
            int il = e/GW, c = e - il*GW;
            float s = 0.f;
            #pragma unroll
            for (int g = 0; g < 25; g++) s += sb[OFF_CP + (g*12 + il)*GW + c];
            g_X1[(b*NN + row0 + il)*GW + c] = s;
        }
    }
}

// ---- conv: X2 = A@X1 (split-K) + Z=[X0,X1,X2] @ W + activation + epilogue ---
template<int FOUT, int CAND>
__device__ __forceinline__ void conv_phase(float* sb, int b, int rk, int tid,
                                           const float* __restrict__ W,
                                           const float* __restrict__ bias)
{
    const float* __restrict__ X0 = CAND ? g_X0c : g_X0r;
    int row0 = rk*12;
    int nrows = (row0 < NN) ? ((NN - row0 < 12) ? NN - row0 : 12) : 0;
    if (nrows > 0){
        for (int e = tid; e < 12*NN; e += NTH){
            int il = e/NN, jj = e - il*NN;
            int r = row0 + (il < nrows ? il : nrows-1);
            sb[e] = g_A[(b*NN + r)*NN + jj];
        }
    }
    __syncthreads();
    if (nrows > 0 && tid < 825){
        int jg = tid/33, c2 = tid - jg*33;
        const float* X1b = g_X1 + b*NN*GW + 2*c2;
        float2 acc[12];
        #pragma unroll
        for (int il = 0; il < 12; il++){ acc[il].x = 0.f; acc[il].y = 0.f; }
        int j0 = jg*8;
        #pragma unroll
        for (int jp = 0; jp < 4; jp++){
            int j = j0 + jp*2;
            float2 x0 = *(const float2*)&X1b[j*GW];
            float2 x1 = *(const float2*)&X1b[(j+1)*GW];
            #pragma unroll
            for (int il = 0; il < 12; il++){
                float2 a = *(const float2*)&sb[il*NN + j];
                acc[il].x = fmaf(a.x, x0.x, acc[il].x);
                acc[il].y = fmaf(a.x, x0.y, acc[il].y);
                acc[il].x = fmaf(a.y, x1.x, acc[il].x);
                acc[il].y = fmaf(a.y, x1.y, acc[il].y);
            }
        }
        #pragma unroll
        for (int il = 0; il < 12; il++)
            *(float2*)&sb[OFF_CP + (jg*12 + il)*GW + 2*c2] = acc[il];
    }
    __syncthreads();
    if (nrows > 0){
        for (int e = tid; e < nrows*GW; e += NTH){
            int il = e/GW, c = e - il*GW;
            float s = 0.f;
            #pragma unroll
            for (int g = 0; g < 25; g++) s += sb[OFF_CP + (g*12 + il)*GW + c];
            int row = (b*NN + row0 + il)*GW + c;
            sb[OFF_Z + il*GIN + 2*GW + c] = s;           // X2
            sb[OFF_Z + il*GIN +   GW + c] = g_X1[row];   // X1
            sb[OFF_Z + il*GIN +        c] = X0[row];     // X0
        }
    }
    __syncthreads();
    constexpr int NF2  = FOUT/2;
    constexpr int QQ   = (FOUT == 128) ? 2 : 1;
    constexpr int NILG = 12/QQ;
    if (nrows > 0 && tid < NF2*NILG){
        int f2  = tid % NF2;
        int il0 = (tid / NF2)*QQ;
        const float2* Wv = (const float2*)W;
        float2 bb = ((const float2*)bias)[f2];
        float2 acc[QQ];
        #pragma unroll
        for (int q = 0; q < QQ; q++) acc[q] = bb;
        #pragma unroll 2
        for (int k = 0; k < GIN; k++){
            float2 w = __ldg(&Wv[k*NF2 + f2]);
            #pragma unroll
            for (int q = 0; q < QQ; q++){
                float zv = sb[OFF_Z + (il0 + q)*GIN + k];
                acc[q].x = fmaf(zv, w.x, acc[q].x);
                acc[q].y = fmaf(zv, w.y, acc[q].y);
            }
        }
        #pragma unroll
        for (int q = 0; q < QQ; q++){
            if (il0 + q < nrows){
                int i = row0 + il0 + q;
                #pragma unroll
                for (int e2 = 0; e2 < 2; e2++){
                    int f = 2*f2 + e2;
                    float a = e2 ? acc[q].y : acc[q].x;
                    if (!CAND){
                        float rv = fsig(a);
                        g_ru[(b*NN + i)*(2*HH) + f] = rv;
                        if (f < HH)
                            g_X0c[(b*NN + i)*GW + CIN + f] = rv * g_state[(b*NN + i)*HH + f];
                    } else {
                        float cv = tanhf(a);
                        float u  = g_ru[(b*NN + i)*(2*HH) + HH + f];
                        float so = g_state[(b*NN + i)*HH + f];
                        float ns = u*so + (1.f - u)*cv;
                        g_state[(b*NN + i)*HH + f] = ns;
                        g_X0r[(b*NN + i)*GW + CIN + f] = ns;
                    }
                }
            }
        }
    }
}

// ============================ grouped megakernel =============================
__global__ void __launch_bounds__(NTH, 1) mega_kernel(
    const float* __restrict__ x,     const float* __restrict__ nf,
    const float* __restrict__ W_s2d, const float* __restrict__ b_s2d,
    const float* __restrict__ W_rz,  const float* __restrict__ b_rz,
    const float* __restrict__ W_h,   const float* __restrict__ b_h,
    const float* __restrict__ Wc2,   const float* __restrict__ bc2,
    const float* __restrict__ Wc1,   const float* __restrict__ bc1,
    const float* __restrict__ Wm2,   const float* __restrict__ bm2,
    const float* __restrict__ Wm1,   const float* __restrict__ bm1,
    const float* __restrict__ W_ru,  const float* __restrict__ b_ru,
    const float* __restrict__ W_cand,const float* __restrict__ b_cand,
    const float* __restrict__ Wp1,   const float* __restrict__ bp1,
    const float* __restrict__ Wp2,   const float* __restrict__ bp2,
    float* __restrict__ out_pred,    float* __restrict__ out_dy)
{
    extern __shared__ float sb[];
    int bid = blockIdx.x, tid = threadIdx.x;
    int grp = bid / GPB, rk = bid - grp*GPB;
    int b = grp;                       // one batch per group
    int warp = tid >> 5, lane = tid & 31;

    // ---------------- init (group-local, batch b only) ----------------
    for (int e = rk*NTH + tid; e < NN*DD; e += GPB*NTH){
        int n = e/DD, d = e - (e/DD)*DD;
        float acc = b_s2d[d];
        for (int k = 0; k < HST; k++) acc = fmaf(nf[n*HST + k], W_s2d[k*DD + d], acc);
        g_state_dy[(b*NN + n)*DD + d] = acc;
    }
    for (int e = rk*NTH + tid; e < NN*HH; e += GPB*NTH) g_state[b*NN*HH + e] = 0.f;
    for (int e = rk*NTH + tid; e < NN*GW; e += GPB*NTH) g_X0r[b*NN*GW + e] = 0.f;
    group_barrier(grp);

    for (int t = 0; t < TT; t++){
        // -------- GRU-dy + P/Q: warp-strided nodes across the group's blocks --------
        {
            int nn = warp*GPB + rk;
            if (nn < NN){
                float* sd = sb + warp*96;
                float* rs = sd + 32;
                float* sv = sd + 64;
                const float* xr = x + ((b*TT + t)*NN + nn)*CIN;
                if (lane < CIN){
                    float xv = xr[lane];
                    g_X0r[(b*NN + nn)*GW + lane] = xv;
                    g_X0c[(b*NN + nn)*GW + lane] = xv;
                }
                float inp1 = xr[0];
                int base = (b*NN + nn)*DD;
                sd[lane] = g_state_dy[base + lane];
                __syncwarp();
                float accr = b_rz[lane]      + inp1 * W_rz[lane];
                float accz = b_rz[lane + 32] + inp1 * W_rz[lane + 32];
                #pragma unroll
                for (int d = 0; d < 32; d++){
                    float v = sd[d];
                    accr = fmaf(v, W_rz[(1 + d)*64 + lane],      accr);
                    accz = fmaf(v, W_rz[(1 + d)*64 + lane + 32], accz);
                }
                float r = fsig(accr), z = fsig(accz);
                rs[lane] = r * sd[lane];
                __syncwarp();
                float acch = b_h[lane] + inp1 * W_h[lane];
                #pragma unroll
                for (int d = 0; d < 32; d++) acch = fmaf(rs[d], W_h[(1 + d)*32 + lane], acch);
                float h  = tanhf(acch);
                float nd = z * sd[lane] + (1.f - z) * h;
                g_state_dy[base + lane] = nd;
                float s = fmaxf(nd, 0.f);
                sv[lane] = s;
                __syncwarp();
                float pg = 0.f, qg = bc2[lane], pm = 0.f, qm = bm2[lane];
                #pragma unroll
                for (int d = 0; d < 32; d++){
                    float v = sv[d];
                    pg = fmaf(v, Wc2[d*32 + lane],        pg);
                    qg = fmaf(v, Wc2[(32 + d)*32 + lane], qg);
                    pm = fmaf(v, Wm2[d*32 + lane],        pm);
                    qm = fmaf(v, Wm2[(32 + d)*32 + lane], qm);
                }
                g_Pg[base + lane] = pg;  g_Qg[base + lane] = qg;
                g_Pm[base + lane] = pm;  g_Qm[base + lane] = qm;
            }
        }
        group_barrier(grp);

        // -------- pair: A = g * sigmoid(m); 64x32 tiles, 2 iterations --------
        {
            if (tid < 32){ sb[P_WG + tid] = Wc1[tid]; sb[P_WM + tid] = Wm1[tid]; }
            float c1b = __ldg(&bc1[0]), m1b = __ldg(&bm1[0]);
            for (int it = 0; it < 2; it++){
                int tile = it*GPB + rk;            // 28 tiles: 4 i-tiles x 7 j-tiles
                bool act = tile < 28;
                int i0 = 0, j0 = 0;
                if (act){ i0 = (tile/7)*64; j0 = (tile - (tile/7)*7)*32; }
                __syncthreads();
                if (act){
                    for (int e = tid; e < 2048; e += NTH){
                        int ril = e >> 5, dd = e & 31;
                        int i = i0 + ril; int ci = i < NN ? i : NN-1;
                        int pidx = (b*NN + ci)*DD + dd;
                        sb[P_PG + ril*34 + dd] = g_Pg[pidx];
                        sb[P_PM + ril*34 + dd] = g_Pm[pidx];
                    }
                    {
                        int jl = tid >> 5, dd = tid & 31;
                        int j = j0 + jl; int cj = j < NN ? j : NN-1;
                        int qidx = (b*NN + cj)*DD + dd;
                        sb[P_QG + jl*34 + dd] = g_Qg[qidx];
                        sb[P_QM + jl*34 + dd] = g_Qm[qidx];
                    }
                }
                __syncthreads();
                if (act){
                    int tj = tid & 31, ti = tid >> 5;
                    int j = j0 + tj;
                    int iA = i0 + ti, iB = i0 + 32 + ti;
                    if (j < NN){
                        float gaA = c1b, maA = m1b, gaB = c1b, maB = m1b;
                        #pragma unroll
                        for (int d = 0; d < 32; d += 2){
                            float2 qg  = *(const float2*)&sb[P_QG + tj*34 + d];
                            float2 qm  = *(const float2*)&sb[P_QM + tj*34 + d];
                            float2 wg  = *(const float2*)&sb[P_WG + d];
                            float2 wm  = *(const float2*)&sb[P_WM + d];
                            float2 pAg = *(const float2*)&sb[P_PG + ti*34 + d];
                            float2 pAm = *(const float2*)&sb[P_PM + ti*34 + d];
                            float2 pBg = *(const float2*)&sb[P_PG + (ti+32)*34 + d];
                            float2 pBm = *(const float2*)&sb[P_PM + (ti+32)*34 + d];
                            gaA = fmaf(fmaxf(pAg.x + qg.x, 0.f), wg.x, gaA);
                            gaA = fmaf(fmaxf(pAg.y + qg.y, 0.f), wg.y, gaA);
                            maA = fmaf(fmaxf(pAm.x + qm.x, 0.f), wm.x, maA);
                            maA = fmaf(fmaxf(pAm.y + qm.y, 0.f), wm.y, maA);
                            gaB = fmaf(fmaxf(pBg.x + qg.x, 0.f), wg.x, gaB);
                            gaB = fmaf(fmaxf(pBg.y + qg.y, 0.f), wg.y, gaB);
                            maB = fmaf(fmaxf(pBm.x + qm.x, 0.f), wm.x, maB);
                            maB = fmaf(fmaxf(pBm.y + qm.y, 0.f), wm.y, maB);
                        }
                        size_t tb = (size_t)t*BN*NN*NN;
                        if (iA < NN){
                            float A = gaA * fsig(maA);
                            int idx = (b*NN + iA)*NN + j;
                            g_A[idx] = A; out_dy[tb + idx] = A;
                        }
                        if (iB < NN){
                            float A = gaB * fsig(maB);
                            int idx = (b*NN + iB)*NN + j;
                            g_A[idx] = A; out_dy[tb + idx] = A;
                        }
                    }
                }
            }
        }
        group_barrier(grp);

        hop_phase(sb, b, rk, tid, g_X0r);
        group_barrier(grp);
        conv_phase<128, 0>(sb, b, rk, tid, W_ru, b_ru);
        group_barrier(grp);
        hop_phase(sb, b, rk, tid, g_X0c);
        group_barrier(grp);
        conv_phase<64, 1>(sb, b, rk, tid, W_cand, b_cand);
        group_barrier(grp);
    }

    // ---------------- prediction head (one warp per node) ----------------
    {
        int nn = warp*GPB + rk;
        if (nn < NN){
            int node = b*NN + nn;
            float s0 = g_state[node*HH + lane];
            float s1 = g_state[node*HH + 32 + lane];
            float a0 = bp1[lane], a1 = bp1[lane + 32];
            #pragma unroll
            for (int k = 0; k < 32; k++){
                float sk = __shfl_sync(0xffffffffu, s0, k);
                a0 = fmaf(sk, Wp1[k*HH + lane],      a0);
                a1 = fmaf(sk, Wp1[k*HH + lane + 32], a1);
            }
            #pragma unroll
            for (int k = 0; k < 32; k++){
                float sk = __shfl_sync(0xffffffffu, s1, k);
                a0 = fmaf(sk, Wp1[(32 + k)*HH + lane],      a0);
                a1 = fmaf(sk, Wp1[(32 + k)*HH + lane + 32], a1);
            }
            float h0 = a0 > 0.f ? a0 : 0.01f*a0;
            float h1 = a1 > 0.f ? a1 : 0.01f*a1;
            float r = h0*Wp2[lane] + h1*Wp2[lane + 32];
            #pragma unroll
            for (int off = 16; off > 0; off >>= 1) r += __shfl_down_sync(0xffffffffu, r, off);
            if (lane == 0) out_pred[node] = r + bp2[0];
        }
    }
}

// ---------------- launch ------------------------------------------------------
extern "C" void kernel_launch(void* const* d_in, const int* in_sizes, int n_in,
                              void* d_out, int out_size)
{
    (void)in_sizes; (void)n_in; (void)out_size;
    const float* x        = (const float*)d_in[0];
    const float* nf       = (const float*)d_in[1];
    const float* W_s2d    = (const float*)d_in[2];
    const float* b_s2d    = (const float*)d_in[3];
    const float* W_rz     = (const float*)d_in[4];
    const float* b_rz     = (const float*)d_in[5];
    const float* W_h      = (const float*)d_in[6];
    const float* b_h      = (const float*)d_in[7];
    const float* Wc2      = (const float*)d_in[8];
    const float* bc2      = (const float*)d_in[9];
    const float* Wc1      = (const float*)d_in[10];
    const float* bc1      = (const float*)d_in[11];
    const float* Wm2      = (const float*)d_in[12];
    const float* bm2      = (const float*)d_in[13];
    const float* Wm1      = (const float*)d_in[14];
    const float* bm1      = (const float*)d_in[15];
    const float* W_ru     = (const float*)d_in[16];
    const float* b_ru     = (const float*)d_in[17];
    const float* W_cand   = (const float*)d_in[18];
    const float* b_cand   = (const float*)d_in[19];
    const float* Wp1      = (const float*)d_in[20];
    const float* bp1      = (const float*)d_in[21];
    const float* Wp2      = (const float*)d_in[22];
    const float* bp2      = (const float*)d_in[23];

    float* out      = (float*)d_out;
    float* out_pred = out;                 // (B,N,1) = 1600 floats
    float* out_dy   = out + BN*NN;         // (T,B,N,N)

    const int SMEM_BYTES = SMEMF * 4;      // 98304
    cudaFuncSetAttribute(mega_kernel, cudaFuncAttributeMaxDynamicSharedMemorySize, SMEM_BYTES);

    mega_kernel<<<GRID, NTH, SMEM_BYTES>>>(x, nf, W_s2d, b_s2d, W_rz, b_rz, W_h, b_h,
                                           Wc2, bc2, Wc1, bc1, Wm2, bm2, Wm1, bm1,
                                           W_ru, b_ru, W_cand, b_cand,
                                           Wp1, bp1, Wp2, bp2, out_pred, out_dy);
}

// round 9
// speedup vs baseline: 1.7104x; 1.1584x over previous
#include <cuda_runtime.h>
#include <math.h>

#define BN   8
#define TT   12
#define NN   200
#define CIN  2
#define HH   64
#define DD   32
#define HST  64
#define GW   66      // CIN + HH
#define GIN  198     // GW * 3
#define GROUPS 8
#define GPB    18
#define GRID   (GROUPS*GPB)   // 144 blocks, <=148 SMs, all co-resident
#define NTH    1024
#define MAXR   12

// ---- smem layout (floats) ----
#define OFF_A    0          // A tile: 12*200 = 2400
#define OFF_P    2400       // Pg 12*32, Pm 12*32 = 768
#define OFF_SD   3168       // state_dy 12*32 = 384
#define OFF_U    3552       // u 12*64 = 768
#define OFF_W    4320       // wc1 32 | wm1 32
#define OFF_GRU  4384       // gru scratch 12 warps * 96 = 1152
#define OFF_CP   5536       // split-K partials 25*12*66 = 19800 (also Q stage)
#define OFF_Z    25336      // Z 12*198 = 2376
#define SMEMF    27712      // *4 = 110848 bytes
#define QS_G     OFF_CP
#define QS_M     (OFF_CP + 6800)   // 200*34

// ---------------- device scratch ----------------
__device__ float g_Qg[BN*NN*DD];
__device__ float g_Qm[BN*NN*DD];
__device__ float g_X1[BN*NN*GW];
__device__ float g_X0r[BN*NN*GW];   // [xt | state]
__device__ float g_X0c[BN*NN*GW];   // [xt | rr*state]
__device__ unsigned g_cnt[GROUPS];
__device__ unsigned g_gen[GROUPS];

__device__ __forceinline__ float fsig(float v){
    return __fdividef(1.f, 1.f + __expf(-v));
}

// group-local barrier among the GPB co-resident blocks of one group
__device__ __forceinline__ void group_barrier(int grp){
    __syncthreads();
    if (threadIdx.x == 0){
        volatile unsigned* vg = &g_gen[grp];
        unsigned gen = *vg;
        __threadfence();
        if (atomicAdd(&g_cnt[grp], 1u) == GPB - 1u){
            g_cnt[grp] = 0u;
            __threadfence();
            *vg = gen + 1u;
        } else {
            while (*vg == gen) { }
        }
        __threadfence();
    }
    __syncthreads();
}

// ---- gru for own rows (warp per local row); writes Q global, P smem, sd smem --
__device__ __forceinline__ void gru_step(float* sb, int b, int row0, int nrows, int t,
    const float* __restrict__ x,
    const float* __restrict__ W_rz, const float* __restrict__ b_rz,
    const float* __restrict__ W_h,  const float* __restrict__ b_h,
    const float* __restrict__ Wc2,  const float* __restrict__ bc2,
    const float* __restrict__ Wm2,  const float* __restrict__ bm2)
{
    int warp = threadIdx.x >> 5, lane = threadIdx.x & 31;
    if (warp < nrows){
        int n  = row0 + warp;
        int gi = b*NN + n;
        float* sdp = sb + OFF_SD  + warp*32;
        float* sc  = sb + OFF_GRU + warp*96;   // rs[32] | sv[32]
        const float* xr = x + ((b*TT + t)*NN + n)*CIN;
        if (lane < CIN){
            float xv = xr[lane];
            g_X0r[gi*GW + lane] = xv;
            g_X0c[gi*GW + lane] = xv;
        }
        float inp1 = __ldg(&xr[0]);
        float sdv  = sdp[lane];
        float accr = b_rz[lane]      + inp1 * W_rz[lane];
        float accz = b_rz[lane + 32] + inp1 * W_rz[lane + 32];
        #pragma unroll
        for (int d = 0; d < 32; d++){
            float v = sdp[d];
            accr = fmaf(v, W_rz[(1 + d)*64 + lane],      accr);
            accz = fmaf(v, W_rz[(1 + d)*64 + lane + 32], accz);
        }
        float r = fsig(accr), z = fsig(accz);
        sc[lane] = r * sdv;
        __syncwarp();
        float acch = b_h[lane] + inp1 * W_h[lane];
        #pragma unroll
        for (int d = 0; d < 32; d++) acch = fmaf(sc[d], W_h[(1 + d)*32 + lane], acch);
        float h  = tanhf(acch);
        float nd = z * sdv + (1.f - z) * h;
        sdp[lane] = nd;
        float s = fmaxf(nd, 0.f);
        sc[32 + lane] = s;
        __syncwarp();
        float pg = 0.f, qg = bc2[lane], pm = 0.f, qm = bm2[lane];
        #pragma unroll
        for (int d = 0; d < 32; d++){
            float v = sc[32 + d];
            pg = fmaf(v, Wc2[d*32 + lane],        pg);
            qg = fmaf(v, Wc2[(32 + d)*32 + lane], qg);
            pm = fmaf(v, Wm2[d*32 + lane],        pm);
            qm = fmaf(v, Wm2[(32 + d)*32 + lane], qm);
        }
        sb[OFF_P +       warp*32 + lane] = pg;
        sb[OFF_P + 384 + warp*32 + lane] = pm;
        g_Qg[gi*DD + lane] = qg;
        g_Qm[gi*DD + lane] = qm;
    }
}

// ---- split-K core: acc rows (<=12) of A_smem @ M(200xGW, global) -> Cp smem --
__device__ __forceinline__ void spmm_partials(float* sb, const float* __restrict__ M,
                                              int b, int tid)
{
    if (tid < 825){
        int jg = tid/33, c2 = tid - jg*33;
        int j0 = jg*8;
        const float* Mb = M + b*NN*GW + 2*c2;
        float2 acc[MAXR];
        #pragma unroll
        for (int il = 0; il < MAXR; il++){ acc[il].x = 0.f; acc[il].y = 0.f; }
        #pragma unroll
        for (int jp = 0; jp < 4; jp++){
            int j = j0 + 2*jp;
            float2 x0 = __ldg((const float2*)&Mb[j*GW]);
            float2 x1 = __ldg((const float2*)&Mb[(j+1)*GW]);
            #pragma unroll
            for (int il = 0; il < MAXR; il++){
                float2 a = *(const float2*)&sb[OFF_A + il*200 + j];
                acc[il].x = fmaf(a.x, x0.x, acc[il].x);
                acc[il].y = fmaf(a.x, x0.y, acc[il].y);
                acc[il].x = fmaf(a.y, x1.x, acc[il].x);
                acc[il].y = fmaf(a.y, x1.y, acc[il].y);
            }
        }
        #pragma unroll
        for (int il = 0; il < MAXR; il++)
            *(float2*)&sb[OFF_CP + (jg*MAXR + il)*66 + 2*c2] = acc[il];
    }
}

// ---- hop: X1 rows = A_smem @ X0 ----
__device__ __forceinline__ void hop_phase(float* sb, int b, int row0, int nrows, int tid,
                                          const float* __restrict__ X0)
{
    spmm_partials(sb, X0, b, tid);
    __syncthreads();
    for (int e = tid; e < nrows*GW; e += NTH){
        int il = e/GW, c = e - il*GW;
        float s = 0.f;
        #pragma unroll
        for (int g = 0; g < 25; g++) s += sb[OFF_CP + (g*MAXR + il)*66 + c];
        g_X1[(b*NN + row0 + il)*GW + c] = s;
    }
}

// ---- conv: X2 = A_smem@X1 ; Z=[X0|X1|X2] @ W + act + epilogue ----
template<int FOUT, int CAND>
__device__ __forceinline__ void conv_phase(float* sb, int b, int row0, int nrows, int tid,
                                           const float* __restrict__ W,
                                           const float* __restrict__ bias)
{
    const float* __restrict__ X0 = CAND ? g_X0c : g_X0r;
    spmm_partials(sb, g_X1, b, tid);
    __syncthreads();
    for (int e = tid; e < nrows*GW; e += NTH){
        int il = e/GW, c = e - il*GW;
        float s = 0.f;
        #pragma unroll
        for (int g = 0; g < 25; g++) s += sb[OFF_CP + (g*MAXR + il)*66 + c];
        int row = (b*NN + row0 + il)*GW + c;
        sb[OFF_Z + il*GIN + 2*GW + c] = s;            // X2
        sb[OFF_Z + il*GIN +   GW + c] = g_X1[row];    // X1
        sb[OFF_Z + il*GIN +        c] = X0[row];      // X0
    }
    __syncthreads();
    constexpr int NF4 = FOUT/4;            // 32 or 16
    constexpr int QQ  = (FOUT == 128) ? 2 : 1;
    constexpr int NT  = NF4 * (MAXR/QQ);   // 192
    if (tid < NT){
        int f4  = tid % NF4;
        int il0 = (tid / NF4)*QQ;
        const float4* Wv = (const float4*)W;
        float4 bb = ((const float4*)bias)[f4];
        float4 acc[QQ];
        #pragma unroll
        for (int q = 0; q < QQ; q++) acc[q] = bb;
        #pragma unroll 2
        for (int k = 0; k < GIN; k++){
            float4 w = __ldg(&Wv[k*NF4 + f4]);
            #pragma unroll
            for (int q = 0; q < QQ; q++){
                float zv = sb[OFF_Z + (il0 + q)*GIN + k];
                acc[q].x = fmaf(zv, w.x, acc[q].x);
                acc[q].y = fmaf(zv, w.y, acc[q].y);
                acc[q].z = fmaf(zv, w.z, acc[q].z);
                acc[q].w = fmaf(zv, w.w, acc[q].w);
            }
        }
        #pragma unroll
        for (int q = 0; q < QQ; q++){
            int il = il0 + q;
            if (il < nrows){
                int gi = b*NN + row0 + il;
                float av[4] = {acc[q].x, acc[q].y, acc[q].z, acc[q].w};
                #pragma unroll
                for (int c = 0; c < 4; c++){
                    int f = 4*f4 + c;
                    float a = av[c];
                    if (!CAND){
                        float rv = fsig(a);
                        if (f < HH){
                            float so = g_X0r[gi*GW + CIN + f];
                            g_X0c[gi*GW + CIN + f] = rv * so;
                        } else {
                            sb[OFF_U + il*HH + (f - HH)] = rv;
                        }
                    } else {
                        float cv = tanhf(a);
                        float u  = sb[OFF_U + il*HH + f];
                        float so = g_X0r[gi*GW + CIN + f];
                        g_X0r[gi*GW + CIN + f] = u*so + (1.f - u)*cv;
                    }
                }
            }
        }
    }
}

// ============================ megakernel =====================================
__global__ void __launch_bounds__(NTH, 1) mega_kernel(
    const float* __restrict__ x,     const float* __restrict__ nf,
    const float* __restrict__ W_s2d, const float* __restrict__ b_s2d,
    const float* __restrict__ W_rz,  const float* __restrict__ b_rz,
    const float* __restrict__ W_h,   const float* __restrict__ b_h,
    const float* __restrict__ Wc2,   const float* __restrict__ bc2,
    const float* __restrict__ Wc1,   const float* __restrict__ bc1,
    const float* __restrict__ Wm2,   const float* __restrict__ bm2,
    const float* __restrict__ Wm1,   const float* __restrict__ bm1,
    const float* __restrict__ W_ru,  const float* __restrict__ b_ru,
    const float* __restrict__ W_cand,const float* __restrict__ b_cand,
    const float* __restrict__ Wp1,   const float* __restrict__ bp1,
    const float* __restrict__ Wp2,   const float* __restrict__ bp2,
    float* __restrict__ out_pred,    float* __restrict__ out_dy)
{
    extern __shared__ float sb[];
    int bid = blockIdx.x, tid = threadIdx.x;
    int grp = bid / GPB, rk = bid - grp*GPB;
    int b = grp;
    int warp = tid >> 5, lane = tid & 31;
    int row0  = rk*11 + (rk < 2 ? rk : 2);
    int nrows = 11 + (rk < 2 ? 1 : 0);

    // ---------------- init: state_dy (smem) + zero X0r state cols ----------------
    for (int e = tid; e < nrows*DD; e += NTH){
        int l = e/DD, d = e - l*DD;
        int n = row0 + l;
        float acc = b_s2d[d];
        #pragma unroll 8
        for (int k = 0; k < HST; k++) acc = fmaf(nf[n*HST + k], W_s2d[k*DD + d], acc);
        sb[OFF_SD + l*DD + d] = acc;
    }
    for (int e = tid; e < nrows*HH; e += NTH){
        int l = e/HH, f = e - l*HH;
        g_X0r[(b*NN + row0 + l)*GW + CIN + f] = 0.f;
    }
    if (tid < 32) sb[OFF_W + tid] = Wc1[tid];
    else if (tid < 64) sb[OFF_W + tid] = Wm1[tid - 32];
    __syncthreads();
    gru_step(sb, b, row0, nrows, 0, x, W_rz, b_rz, W_h, b_h, Wc2, bc2, Wm2, bm2);
    group_barrier(grp);

    float bc1v = __ldg(&bc1[0]), bm1v = __ldg(&bm1[0]);

    for (int t = 0; t < TT; t++){
        // -------- phase 1: pair (A rows -> smem + out_dy) then hop_r --------
        {
            // stage Q into smem
            for (int e = tid; e < NN*DD; e += NTH){
                int j = e >> 5, d = e & 31;
                sb[QS_G + j*34 + d] = g_Qg[b*NN*DD + e];
                sb[QS_M + j*34 + d] = g_Qm[b*NN*DD + e];
            }
            __syncthreads();
            if (tid < 800){
                int j  = tid % 200;
                int ig = tid / 200;         // 0..3, each 3 local rows
                float ga[3] = {bc1v, bc1v, bc1v};
                float ma[3] = {bm1v, bm1v, bm1v};
                #pragma unroll
                for (int dp = 0; dp < 16; dp++){
                    float2 qg = *(const float2*)&sb[QS_G + j*34 + 2*dp];
                    float2 qm = *(const float2*)&sb[QS_M + j*34 + 2*dp];
                    float2 wg = *(const float2*)&sb[OFF_W + 2*dp];
                    float2 wm = *(const float2*)&sb[OFF_W + 32 + 2*dp];
                    #pragma unroll
                    for (int q = 0; q < 3; q++){
                        int l = ig*3 + q;
                        float2 pg = *(const float2*)&sb[OFF_P +       l*32 + 2*dp];
                        float2 pm = *(const float2*)&sb[OFF_P + 384 + l*32 + 2*dp];
                        ga[q] = fmaf(fmaxf(pg.x + qg.x, 0.f), wg.x, ga[q]);
                        ga[q] = fmaf(fmaxf(pg.y + qg.y, 0.f), wg.y, ga[q]);
                        ma[q] = fmaf(fmaxf(pm.x + qm.x, 0.f), wm.x, ma[q]);
                        ma[q] = fmaf(fmaxf(pm.y + qm.y, 0.f), wm.y, ma[q]);
                    }
                }
                #pragma unroll
                for (int q = 0; q < 3; q++){
                    int l = ig*3 + q;
                    if (l < nrows){
                        float A = ga[q] * fsig(ma[q]);
                        sb[OFF_A + l*200 + j] = A;
                        out_dy[(((size_t)t*BN + b)*NN + row0 + l)*NN + j] = A;
                    }
                }
            }
            __syncthreads();
            hop_phase(sb, b, row0, nrows, tid, g_X0r);
        }
        group_barrier(grp);

        conv_phase<128, 0>(sb, b, row0, nrows, tid, W_ru, b_ru);
        group_barrier(grp);

        hop_phase(sb, b, row0, nrows, tid, g_X0c);
        group_barrier(grp);

        conv_phase<64, 1>(sb, b, row0, nrows, tid, W_cand, b_cand);
        if (t < TT-1){
            __syncthreads();
            gru_step(sb, b, row0, nrows, t+1, x, W_rz, b_rz, W_h, b_h, Wc2, bc2, Wm2, bm2);
        }
        group_barrier(grp);
    }

    // ---------------- prediction head (own rows; no barrier needed) -------------
    if (warp < nrows){
        int gi = b*NN + row0 + warp;
        float s0 = g_X0r[gi*GW + CIN + lane];
        float s1 = g_X0r[gi*GW + CIN + 32 + lane];
        float a0 = bp1[lane], a1 = bp1[lane + 32];
        #pragma unroll
        for (int k = 0; k < 32; k++){
            float sk = __shfl_sync(0xffffffffu, s0, k);
            a0 = fmaf(sk, Wp1[k*HH + lane],      a0);
            a1 = fmaf(sk, Wp1[k*HH + lane + 32], a1);
        }
        #pragma unroll
        for (int k = 0; k < 32; k++){
            float sk = __shfl_sync(0xffffffffu, s1, k);
            a0 = fmaf(sk, Wp1[(32 + k)*HH + lane],      a0);
            a1 = fmaf(sk, Wp1[(32 + k)*HH + lane + 32], a1);
        }
        float h0 = a0 > 0.f ? a0 : 0.01f*a0;
        float h1 = a1 > 0.f ? a1 : 0.01f*a1;
        float r = h0*Wp2[lane] + h1*Wp2[lane + 32];
        #pragma unroll
        for (int off = 16; off > 0; off >>= 1) r += __shfl_down_sync(0xffffffffu, r, off);
        if (lane == 0) out_pred[gi] = r + bp2[0];
    }
}

// ---------------- launch ------------------------------------------------------
extern "C" void kernel_launch(void* const* d_in, const int* in_sizes, int n_in,
                              void* d_out, int out_size)
{
    (void)in_sizes; (void)n_in; (void)out_size;
    const float* x        = (const float*)d_in[0];
    const float* nf       = (const float*)d_in[1];
    const float* W_s2d    = (const float*)d_in[2];
    const float* b_s2d    = (const float*)d_in[3];
    const float* W_rz     = (const float*)d_in[4];
    const float* b_rz     = (const float*)d_in[5];
    const float* W_h      = (const float*)d_in[6];
    const float* b_h      = (const float*)d_in[7];
    const float* Wc2      = (const float*)d_in[8];
    const float* bc2      = (const float*)d_in[9];
    const float* Wc1      = (const float*)d_in[10];
    const float* bc1      = (const float*)d_in[11];
    const float* Wm2      = (const float*)d_in[12];
    const float* bm2      = (const float*)d_in[13];
    const float* Wm1      = (const float*)d_in[14];
    const float* bm1      = (const float*)d_in[15];
    const float* W_ru     = (const float*)d_in[16];
    const float* b_ru     = (const float*)d_in[17];
    const float* W_cand   = (const float*)d_in[18];
    const float* b_cand   = (const float*)d_in[19];
    const float* Wp1      = (const float*)d_in[20];
    const float* bp1      = (const float*)d_in[21];
    const float* Wp2      = (const float*)d_in[22];
    const float* bp2      = (const float*)d_in[23];

    float* out      = (float*)d_out;
    float* out_pred = out;                 // (B,N,1) = 1600 floats
    float* out_dy   = out + BN*NN;         // (T,B,N,N)

    const int SMEM_BYTES = SMEMF * 4;      // 110848
    cudaFuncSetAttribute(mega_kernel, cudaFuncAttributeMaxDynamicSharedMemorySize, SMEM_BYTES);

    mega_kernel<<<GRID, NTH, SMEM_BYTES>>>(x, nf, W_s2d, b_s2d, W_rz, b_rz, W_h, b_h,
                                           Wc2, bc2, Wc1, bc1, Wm2, bm2, Wm1, bm1,
                                           W_ru, b_ru, W_cand, b_cand,
                                           Wp1, bp1, Wp2, bp2, out_pred, out_dy);
}